// round 3
// baseline (speedup 1.0000x reference)
#include <cuda_runtime.h>

#define Hdim 128
#define NNODES 50000
#define NEDGES 800000
#define TILE 64
#define LDA 66   // padded feature-major stride (even => 8B-aligned pairs)

__device__ int   g_is64;
__device__ float g_mi[(long long)NNODES * Hdim];  // segment-summed m_i scratch
__device__ float g_P [(long long)NNODES * Hdim];  // h @ We1[0:128]   + be1
__device__ float g_Q [(long long)NNODES * Hdim];  // h @ We1[128:256]

// ---------- f32x2 helpers ----------
__device__ __forceinline__ unsigned long long pk2(float lo, float hi) {
    unsigned long long r;
    asm("mov.b64 %0, {%1,%2};" : "=l"(r) : "f"(lo), "f"(hi));
    return r;
}
__device__ __forceinline__ void upk2(unsigned long long v, float& lo, float& hi) {
    asm("mov.b64 {%0,%1}, %2;" : "=f"(lo), "=f"(hi) : "l"(v));
}
#define FMA2(d, a, b) asm("fma.rn.f32x2 %0, %1, %2, %0;" : "+l"(d) : "l"(a), "l"(b))

__device__ __forceinline__ void red_add_v4(float* p, float a, float b, float c, float d) {
    asm volatile("red.global.add.v4.f32 [%0], {%1,%2,%3,%4};"
                 :: "l"(p), "f"(a), "f"(b), "f"(c), "f"(d) : "memory");
}

__device__ __forceinline__ float silu_f(float v) { return v / (1.0f + __expf(-v)); }

// ---------- GEMM tile: C[64 rows x 128 cols] = A[64 x K] * W[K x 128] (+ bias) ----------
// 128 threads. lane&15 = tx -> cols tx*8..tx*8+7 ; row group ry=(lane>>4)+wid*2 ->
// rows r0=ry*8..r0+7 as 4 packed pairs. Per k: 2 LDG.128 (W) + 4 LDS.64 (A, broadcast
// within 16-lane groups) + 32 FFMA2  => FMA-pipe-bound.
template <int K>
__device__ __forceinline__ void gemm_tile8(const float* __restrict__ As,
                                           const float* __restrict__ W,
                                           const float* __restrict__ bias,
                                           unsigned long long acc[4][8],
                                           int tx, int r0) {
    float4 b0, b1;
    if (bias) {
        b0 = __ldg((const float4*)(bias + tx * 8));
        b1 = __ldg((const float4*)(bias + tx * 8 + 4));
    } else {
        b0 = make_float4(0.f, 0.f, 0.f, 0.f);
        b1 = b0;
    }
#pragma unroll
    for (int i = 0; i < 4; i++) {
        acc[i][0] = pk2(b0.x, b0.x); acc[i][1] = pk2(b0.y, b0.y);
        acc[i][2] = pk2(b0.z, b0.z); acc[i][3] = pk2(b0.w, b0.w);
        acc[i][4] = pk2(b1.x, b1.x); acc[i][5] = pk2(b1.y, b1.y);
        acc[i][6] = pk2(b1.z, b1.z); acc[i][7] = pk2(b1.w, b1.w);
    }
#pragma unroll 4
    for (int k = 0; k < K; k++) {
        float4 wA = __ldg((const float4*)(W + (long long)k * Hdim + tx * 8));
        float4 wB = __ldg((const float4*)(W + (long long)k * Hdim + tx * 8 + 4));
        unsigned long long w[8];
        w[0] = pk2(wA.x, wA.x); w[1] = pk2(wA.y, wA.y);
        w[2] = pk2(wA.z, wA.z); w[3] = pk2(wA.w, wA.w);
        w[4] = pk2(wB.x, wB.x); w[5] = pk2(wB.y, wB.y);
        w[6] = pk2(wB.z, wB.z); w[7] = pk2(wB.w, wB.w);
        const float* ak = As + k * LDA + r0;
#pragma unroll
        for (int i = 0; i < 4; i++) {
            unsigned long long a2 = *(const unsigned long long*)(ak + 2 * i);
#pragma unroll
            for (int j = 0; j < 8; j++) FMA2(acc[i][j], a2, w[j]);
        }
    }
}

// ---------- index dtype detection (int32 vs int64) ----------
__global__ void detect_kernel(const int* ei32) {
    if (blockIdx.x == 0 && threadIdx.x == 0) {
        int f = 1;
        for (int i = 0; i < 1024; i++) {
            if (ei32[2 * i + 1] != 0) { f = 0; break; }
        }
        g_is64 = f;
    }
}

// ---------- init: zero m_i scratch, seed out_x = x ----------
__global__ void init_kernel(const float* __restrict__ x, float* __restrict__ out_x) {
    long long i = (long long)blockIdx.x * blockDim.x + threadIdx.x;
    if (i < (long long)NNODES * Hdim) g_mi[i] = 0.0f;
    if (i < (long long)NNODES * 3)    out_x[i] = x[i];
}

// ---------- prep: P = h @ We1[0:128] + be1 ; Q = h @ We1[128:256] ----------
__global__ void __launch_bounds__(128, 4) prep_kernel(
    const float* __restrict__ h,
    const float* __restrict__ We1, const float* __restrict__ be1) {
    extern __shared__ float sm[];
    float* As = sm;  // 128 * LDA

    const int tid = threadIdx.x;
    const int wid = tid >> 5, lane = tid & 31;
    const int tx = lane & 15;
    const int r0 = ((lane >> 4) + wid * 2) * 8;
    const int nb = blockIdx.x * TILE;

    // gather h feature-major (32 lanes cover 128 cols; 4 warps stride edges)
    for (int e = wid; e < TILE; e += 4) {
        const int node = nb + e;
        const int d0 = lane * 4;
        float4 hv = make_float4(0.f, 0.f, 0.f, 0.f);
        if (node < NNODES) hv = __ldg((const float4*)(h + (long long)node * Hdim + d0));
        As[(d0 + 0) * LDA + e] = hv.x;
        As[(d0 + 1) * LDA + e] = hv.y;
        As[(d0 + 2) * LDA + e] = hv.z;
        As[(d0 + 3) * LDA + e] = hv.w;
    }
    __syncthreads();

    unsigned long long acc[4][8];

    gemm_tile8<128>(As, We1, be1, acc, tx, r0);
#pragma unroll
    for (int i = 0; i < 4; i++) {
        const int n0 = nb + r0 + 2 * i, n1 = n0 + 1;
        float lo[8], hi[8];
#pragma unroll
        for (int j = 0; j < 8; j++) upk2(acc[i][j], lo[j], hi[j]);
        if (n0 < NNODES) {
            *(float4*)(g_P + (long long)n0 * Hdim + tx * 8)     = make_float4(lo[0], lo[1], lo[2], lo[3]);
            *(float4*)(g_P + (long long)n0 * Hdim + tx * 8 + 4) = make_float4(lo[4], lo[5], lo[6], lo[7]);
        }
        if (n1 < NNODES) {
            *(float4*)(g_P + (long long)n1 * Hdim + tx * 8)     = make_float4(hi[0], hi[1], hi[2], hi[3]);
            *(float4*)(g_P + (long long)n1 * Hdim + tx * 8 + 4) = make_float4(hi[4], hi[5], hi[6], hi[7]);
        }
    }

    gemm_tile8<128>(As, We1 + 128 * Hdim, (const float*)0, acc, tx, r0);
#pragma unroll
    for (int i = 0; i < 4; i++) {
        const int n0 = nb + r0 + 2 * i, n1 = n0 + 1;
        float lo[8], hi[8];
#pragma unroll
        for (int j = 0; j < 8; j++) upk2(acc[i][j], lo[j], hi[j]);
        if (n0 < NNODES) {
            *(float4*)(g_Q + (long long)n0 * Hdim + tx * 8)     = make_float4(lo[0], lo[1], lo[2], lo[3]);
            *(float4*)(g_Q + (long long)n0 * Hdim + tx * 8 + 4) = make_float4(lo[4], lo[5], lo[6], lo[7]);
        }
        if (n1 < NNODES) {
            *(float4*)(g_Q + (long long)n1 * Hdim + tx * 8)     = make_float4(hi[0], hi[1], hi[2], hi[3]);
            *(float4*)(g_Q + (long long)n1 * Hdim + tx * 8 + 4) = make_float4(hi[4], hi[5], hi[6], hi[7]);
        }
    }
}

// ---------- edge kernel: m1 via gather-add, then 2 fused GEMM layers ----------
__global__ void __launch_bounds__(128, 4) edge_kernel(
    const float* __restrict__ x, const void* __restrict__ ei,
    const float* __restrict__ We1,
    const float* __restrict__ We2, const float* __restrict__ be2,
    const float* __restrict__ Wc1, const float* __restrict__ bc1,
    const float* __restrict__ Wc2,
    float* __restrict__ out_x) {
    extern __shared__ float sm[];
    float* As = sm;                      // 128 * LDA (m1, later m_ij)
    float* nd = As + 128 * LDA;          // 3 * TILE (normalized coord diffs)
    float* d2s = nd + 3 * TILE;          // TILE (radial)
    int*  rowi = (int*)(d2s + TILE);     // TILE
    int*  coli = rowi + TILE;            // TILE

    const int tid = threadIdx.x;
    const int wid = tid >> 5, lane = tid & 31;
    const int tx = lane & 15;
    const int r0 = ((lane >> 4) + wid * 2) * 8;
    const int eb = blockIdx.x * TILE;
    const int is64 = g_is64;

    // 1) indices + coord geometry
    if (tid < TILE) {
        int e = tid;
        long long r, c;
        if (is64) {
            const long long* p = (const long long*)ei;
            r = p[eb + e]; c = p[NEDGES + eb + e];
        } else {
            const int* p = (const int*)ei;
            r = p[eb + e]; c = p[NEDGES + eb + e];
        }
        rowi[e] = (int)r; coli[e] = (int)c;
        float dx = __ldg(x + r * 3 + 0) - __ldg(x + c * 3 + 0);
        float dy = __ldg(x + r * 3 + 1) - __ldg(x + c * 3 + 1);
        float dz = __ldg(x + r * 3 + 2) - __ldg(x + c * 3 + 2);
        float d2 = dx * dx + dy * dy + dz * dz;
        float dist = sqrtf(d2);
        d2s[e] = d2;
        float inv = 1.0f / (dist + 1e-8f);
        nd[0 * TILE + e] = dx * inv;
        nd[1 * TILE + e] = dy * inv;
        nd[2 * TILE + e] = dz * inv;
    }
    __syncthreads();

    // 2) m1 = silu(P[row] + Q[col] + d2 * We1[256]) — layer-1 GEMM eliminated
    {
        const int d0 = lane * 4;
        float4 w1c = __ldg((const float4*)(We1 + 256 * Hdim + d0));
        for (int e = wid; e < TILE; e += 4) {
            const long long rr = rowi[e], cc = coli[e];
            float4 p = __ldg((const float4*)(g_P + rr * Hdim + d0));
            float4 q = __ldg((const float4*)(g_Q + cc * Hdim + d0));
            const float d2 = d2s[e];
            As[(d0 + 0) * LDA + e] = silu_f(fmaf(d2, w1c.x, p.x + q.x));
            As[(d0 + 1) * LDA + e] = silu_f(fmaf(d2, w1c.y, p.y + q.y));
            As[(d0 + 2) * LDA + e] = silu_f(fmaf(d2, w1c.z, p.z + q.z));
            As[(d0 + 3) * LDA + e] = silu_f(fmaf(d2, w1c.w, p.w + q.w));
        }
    }
    __syncthreads();

    unsigned long long acc[4][8];

    // 3) m_ij = silu(m1 @ We2 + be2); scatter to m_i from registers; stash in As
    gemm_tile8<128>(As, We2, be2, acc, tx, r0);
#pragma unroll
    for (int i = 0; i < 4; i++) {
        float lo[8], hi[8];
#pragma unroll
        for (int j = 0; j < 8; j++) {
            float v0, v1; upk2(acc[i][j], v0, v1);
            lo[j] = silu_f(v0); hi[j] = silu_f(v1);
            acc[i][j] = pk2(lo[j], hi[j]);
        }
        const int e0 = r0 + 2 * i, e1 = e0 + 1;
        float* p0 = g_mi + (long long)rowi[e0] * Hdim + tx * 8;
        float* p1 = g_mi + (long long)rowi[e1] * Hdim + tx * 8;
        red_add_v4(p0,     lo[0], lo[1], lo[2], lo[3]);
        red_add_v4(p0 + 4, lo[4], lo[5], lo[6], lo[7]);
        red_add_v4(p1,     hi[0], hi[1], hi[2], hi[3]);
        red_add_v4(p1 + 4, hi[4], hi[5], hi[6], hi[7]);
    }
    __syncthreads();  // everyone done reading m1
#pragma unroll
    for (int i = 0; i < 4; i++)
#pragma unroll
        for (int j = 0; j < 8; j++)
            *(unsigned long long*)(As + (tx * 8 + j) * LDA + r0 + 2 * i) = acc[i][j];
    __syncthreads();

    // 4) c1 = silu(m_ij @ Wc1 + bc1); s = tanh(c1 . Wc2) * 0.1; force scatter
    gemm_tile8<128>(As, Wc1, bc1, acc, tx, r0);
    float4 wc0 = __ldg((const float4*)(Wc2 + tx * 8));
    float4 wc1 = __ldg((const float4*)(Wc2 + tx * 8 + 4));
    float wcv[8] = {wc0.x, wc0.y, wc0.z, wc0.w, wc1.x, wc1.y, wc1.z, wc1.w};
    float par[8];
#pragma unroll
    for (int i = 0; i < 4; i++) {
        float p0 = 0.0f, p1 = 0.0f;
#pragma unroll
        for (int j = 0; j < 8; j++) {
            float v0, v1; upk2(acc[i][j], v0, v1);
            p0 = fmaf(silu_f(v0), wcv[j], p0);
            p1 = fmaf(silu_f(v1), wcv[j], p1);
        }
        par[2 * i] = p0; par[2 * i + 1] = p1;
    }
#pragma unroll
    for (int i = 0; i < 8; i++) {
#pragma unroll
        for (int off = 8; off > 0; off >>= 1)
            par[i] += __shfl_xor_sync(0xffffffffu, par[i], off);
    }
    if (tx == 0) {
#pragma unroll
        for (int i = 0; i < 8; i++) {
            const int e = r0 + i;
            const float s = tanhf(par[i]) * 0.1f;
            float* px = out_x + (long long)rowi[e] * 3;
            atomicAdd(px + 0, nd[0 * TILE + e] * s);
            atomicAdd(px + 1, nd[1 * TILE + e] * s);
            atomicAdd(px + 2, nd[2 * TILE + e] * s);
        }
    }
}

// ---------- node kernel: node MLP + residual + LayerNorm ----------
__global__ void __launch_bounds__(128, 3) node_kernel(
    const float* __restrict__ h,
    const float* __restrict__ Wn1, const float* __restrict__ bn1,
    const float* __restrict__ Wn2, const float* __restrict__ bn2,
    const float* __restrict__ lng, const float* __restrict__ lnb,
    float* __restrict__ out_h) {
    extern __shared__ float sm[];
    float* As = sm;  // 256 * LDA (node_input, rows 0..127 later reused for B)

    const int tid = threadIdx.x;
    const int wid = tid >> 5, lane = tid & 31;
    const int tx = lane & 15;
    const int r0 = ((lane >> 4) + wid * 2) * 8;
    const int nb = blockIdx.x * TILE;

    // gather [h ; m_i] feature-major
    for (int e = wid; e < TILE; e += 4) {
        const int node = nb + e;
        const int d0 = lane * 4;
        if (node < NNODES) {
            float4 hv = __ldg((const float4*)(h + (long long)node * Hdim + d0));
            As[(d0 + 0) * LDA + e] = hv.x;
            As[(d0 + 1) * LDA + e] = hv.y;
            As[(d0 + 2) * LDA + e] = hv.z;
            As[(d0 + 3) * LDA + e] = hv.w;
            float4 mv = *(const float4*)(g_mi + (long long)node * Hdim + d0);
            As[(Hdim + d0 + 0) * LDA + e] = mv.x;
            As[(Hdim + d0 + 1) * LDA + e] = mv.y;
            As[(Hdim + d0 + 2) * LDA + e] = mv.z;
            As[(Hdim + d0 + 3) * LDA + e] = mv.w;
        } else {
#pragma unroll
            for (int q = 0; q < 4; q++) {
                As[(d0 + q) * LDA + e] = 0.0f;
                As[(Hdim + d0 + q) * LDA + e] = 0.0f;
            }
        }
    }
    __syncthreads();

    unsigned long long acc[4][8];
    gemm_tile8<256>(As, Wn1, bn1, acc, tx, r0);
#pragma unroll
    for (int i = 0; i < 4; i++)
#pragma unroll
        for (int j = 0; j < 8; j++) {
            float v0, v1; upk2(acc[i][j], v0, v1);
            acc[i][j] = pk2(silu_f(v0), silu_f(v1));
        }
    __syncthreads();  // done reading node_input
#pragma unroll
    for (int i = 0; i < 4; i++)
#pragma unroll
        for (int j = 0; j < 8; j++)
            *(unsigned long long*)(As + (tx * 8 + j) * LDA + r0 + 2 * i) = acc[i][j];
    __syncthreads();

    gemm_tile8<128>(As, Wn2, bn2, acc, tx, r0);

    // residual + LayerNorm, processed per row-pair to bound register pressure
    float4 g0 = __ldg((const float4*)(lng + tx * 8));
    float4 g1 = __ldg((const float4*)(lng + tx * 8 + 4));
    float4 bb0 = __ldg((const float4*)(lnb + tx * 8));
    float4 bb1 = __ldg((const float4*)(lnb + tx * 8 + 4));
    float gv[8] = {g0.x, g0.y, g0.z, g0.w, g1.x, g1.y, g1.z, g1.w};
    float bv[8] = {bb0.x, bb0.y, bb0.z, bb0.w, bb1.x, bb1.y, bb1.z, bb1.w};
#pragma unroll
    for (int i = 0; i < 4; i++) {
        const int n0 = nb + r0 + 2 * i, n1 = n0 + 1;
        float4 hA0 = make_float4(0.f, 0.f, 0.f, 0.f), hA1 = hA0, hB0 = hA0, hB1 = hA0;
        if (n0 < NNODES) {
            hA0 = __ldg((const float4*)(h + (long long)n0 * Hdim + tx * 8));
            hA1 = __ldg((const float4*)(h + (long long)n0 * Hdim + tx * 8 + 4));
        }
        if (n1 < NNODES) {
            hB0 = __ldg((const float4*)(h + (long long)n1 * Hdim + tx * 8));
            hB1 = __ldg((const float4*)(h + (long long)n1 * Hdim + tx * 8 + 4));
        }
        float hav[8] = {hA0.x, hA0.y, hA0.z, hA0.w, hA1.x, hA1.y, hA1.z, hA1.w};
        float hbv[8] = {hB0.x, hB0.y, hB0.z, hB0.w, hB1.x, hB1.y, hB1.z, hB1.w};
        float vA[8], vB[8];
        float sA = 0.f, qA = 0.f, sB = 0.f, qB = 0.f;
#pragma unroll
        for (int j = 0; j < 8; j++) {
            float v0, v1; upk2(acc[i][j], v0, v1);
            vA[j] = v0 + hav[j]; vB[j] = v1 + hbv[j];
            sA += vA[j]; qA = fmaf(vA[j], vA[j], qA);
            sB += vB[j]; qB = fmaf(vB[j], vB[j], qB);
        }
#pragma unroll
        for (int off = 8; off > 0; off >>= 1) {
            sA += __shfl_xor_sync(0xffffffffu, sA, off);
            qA += __shfl_xor_sync(0xffffffffu, qA, off);
            sB += __shfl_xor_sync(0xffffffffu, sB, off);
            qB += __shfl_xor_sync(0xffffffffu, qB, off);
        }
        const float muA = sA * (1.0f / 128.0f);
        const float rstdA = rsqrtf(qA * (1.0f / 128.0f) - muA * muA + 1e-5f);
        const float muB = sB * (1.0f / 128.0f);
        const float rstdB = rsqrtf(qB * (1.0f / 128.0f) - muB * muB + 1e-5f);
        float oA[8], oB[8];
#pragma unroll
        for (int j = 0; j < 8; j++) {
            oA[j] = (vA[j] - muA) * rstdA * gv[j] + bv[j];
            oB[j] = (vB[j] - muB) * rstdB * gv[j] + bv[j];
        }
        if (n0 < NNODES) {
            *(float4*)(out_h + (long long)n0 * Hdim + tx * 8)     = make_float4(oA[0], oA[1], oA[2], oA[3]);
            *(float4*)(out_h + (long long)n0 * Hdim + tx * 8 + 4) = make_float4(oA[4], oA[5], oA[6], oA[7]);
        }
        if (n1 < NNODES) {
            *(float4*)(out_h + (long long)n1 * Hdim + tx * 8)     = make_float4(oB[0], oB[1], oB[2], oB[3]);
            *(float4*)(out_h + (long long)n1 * Hdim + tx * 8 + 4) = make_float4(oB[4], oB[5], oB[6], oB[7]);
        }
    }
}

// ---------- launch ----------
extern "C" void kernel_launch(void* const* d_in, const int* in_sizes, int n_in,
                              void* d_out, int out_size) {
    const float* h   = (const float*)d_in[0];
    const float* x   = (const float*)d_in[1];
    const void*  ei  = d_in[2];
    const float* We1 = (const float*)d_in[3];
    const float* be1 = (const float*)d_in[4];
    const float* We2 = (const float*)d_in[5];
    const float* be2 = (const float*)d_in[6];
    const float* Wc1 = (const float*)d_in[7];
    const float* bc1 = (const float*)d_in[8];
    const float* Wc2 = (const float*)d_in[9];
    const float* Wn1 = (const float*)d_in[10];
    const float* bn1 = (const float*)d_in[11];
    const float* Wn2 = (const float*)d_in[12];
    const float* bn2 = (const float*)d_in[13];
    const float* lng = (const float*)d_in[14];
    const float* lnb = (const float*)d_in[15];

    float* out_h = (float*)d_out;
    float* out_x = out_h + (long long)NNODES * Hdim;

    const int SMEM_PREP = (128 * LDA) * 4;
    const int SMEM_EDGE = (128 * LDA + 3 * TILE + TILE + 2 * TILE) * 4;
    const int SMEM_NODE = (256 * LDA) * 4;

    cudaFuncSetAttribute(prep_kernel, cudaFuncAttributeMaxDynamicSharedMemorySize, SMEM_PREP);
    cudaFuncSetAttribute(edge_kernel, cudaFuncAttributeMaxDynamicSharedMemorySize, SMEM_EDGE);
    cudaFuncSetAttribute(node_kernel, cudaFuncAttributeMaxDynamicSharedMemorySize, SMEM_NODE);

    detect_kernel<<<1, 32>>>((const int*)ei);
    init_kernel<<<((long long)NNODES * Hdim + 255) / 256, 256>>>(x, out_x);
    prep_kernel<<<(NNODES + TILE - 1) / TILE, 128, SMEM_PREP>>>(h, We1, be1);
    edge_kernel<<<NEDGES / TILE, 128, SMEM_EDGE>>>(x, ei, We1, We2, be2,
                                                   Wc1, bc1, Wc2, out_x);
    node_kernel<<<(NNODES + TILE - 1) / TILE, 128, SMEM_NODE>>>(h, Wn1, bn1, Wn2, bn2,
                                                                lng, lnb, out_h);
}